// round 9
// baseline (speedup 1.0000x reference)
#include <cuda_runtime.h>
#include <cuda_bf16.h>
#include <cuda_fp16.h>
#include <cstddef>
#include <cstdint>

// ---------------------------------------------------------------------------
// 2-layer GCN. Layer math:
//   xw = A @ W           (tensor cores, bf16 hi/lo split, fp32 accum)
//   agg[d] = dinv[d]*xw[d] + sum_{(u->d)} dinv[u]*xw[u]   (layer 1: dinv in gather)
//   h = dinv*agg + b     (fused into next GEMM's A staging / gather2 epilogue)
// CSR build overlapped with GEMM1 via fat kernels (count+gemmA, fill+gemmB).
// ---------------------------------------------------------------------------

#define NMAX 100000
#define EMAX 1700000
#define HID 128
#define ODIM 64
#define SCAN_BLK 512
#define KP 72   // padded K-chunk stride (conflict-free frag LDS)

#define AUX1 232       // count blocks in FAT1
#define AUX2 232       // fill blocks in FAT2
#define GSPLIT 320     // gemm1 blocks in FAT1; rest in FAT2

__device__ float  g_dinv[NMAX];
__device__ __align__(16) __half g_s1[(size_t)NMAX * HID];     // raw xw, fp16
__device__ __align__(16) __half g_agg1h[(size_t)NMAX * HID];  // fp16 aggregate
__device__ __align__(16) __half g_s2[(size_t)NMAX * ODIM];    // dinv*h1W, fp16
__device__ int    g_is64;

__device__ int g_cnt[NMAX];
__device__ int g_rowptr[NMAX + 1];
__device__ int g_cursor[NMAX];
__device__ int g_csr[EMAX];
__device__ int g_bsum[1024];

__device__ __align__(16) __nv_bfloat16 g_w1t_hi[HID * HID], g_w1t_lo[HID * HID];   // [n][k]
__device__ __align__(16) __nv_bfloat16 g_w2t_hi[ODIM * HID], g_w2t_lo[ODIM * HID]; // [n][k]

// ---- fused pre-pass: dtype detect + cnt zero + W conversion -----------------
__global__ void k_pre(const int* __restrict__ ew,
                      const float* __restrict__ W1, const float* __restrict__ W2, int n)
{
    int i = blockIdx.x * blockDim.x + threadIdx.x;

    if (blockIdx.x == 0) {
        __shared__ int any;
        if (threadIdx.x == 0) any = 0;
        __syncthreads();
        for (int j = threadIdx.x; j < 2048; j += blockDim.x)
            if (ew[2 * j + 1] != 0) any = 1;
        __syncthreads();
        if (threadIdx.x == 0) g_is64 = (any == 0) ? 1 : 0;
    }

    if (i < n) g_cnt[i] = 0;

    if (i < HID * HID) {
        int nn = i >> 7, k = i & 127;
        float v = W1[k * HID + nn];
        __nv_bfloat16 h = __float2bfloat16(v);
        g_w1t_hi[i] = h;
        g_w1t_lo[i] = __float2bfloat16(v - __bfloat162float(h));
    }
    if (i < ODIM * HID) {
        int nn = i >> 7, k = i & 127;
        float v = W2[k * ODIM + nn];
        __nv_bfloat16 h = __float2bfloat16(v);
        g_w2t_hi[i] = h;
        g_w2t_lo[i] = __float2bfloat16(v - __bfloat162float(h));
    }
}

__device__ __forceinline__ int edge_at(const int* __restrict__ w, int i, int is64) {
    return is64 ? w[2 * (size_t)i] : w[i];
}

// ---- scan (3 kernels) --------------------------------------------------------
__global__ void k_scan1(int n) {
    __shared__ int sh[SCAN_BLK];
    int i = blockIdx.x * SCAN_BLK + threadIdx.x;
    int v = (i < n) ? g_cnt[i] : 0;
    sh[threadIdx.x] = v;
    __syncthreads();
    for (int off = 1; off < SCAN_BLK; off <<= 1) {
        int t = (threadIdx.x >= off) ? sh[threadIdx.x - off] : 0;
        __syncthreads();
        sh[threadIdx.x] += t;
        __syncthreads();
    }
    if (i < n) g_rowptr[i] = sh[threadIdx.x] - v;
    if (threadIdx.x == SCAN_BLK - 1) g_bsum[blockIdx.x] = sh[SCAN_BLK - 1];
}

__global__ void k_scan2(int nblk) {
    __shared__ int sh[1024];
    int v = (threadIdx.x < nblk) ? g_bsum[threadIdx.x] : 0;
    sh[threadIdx.x] = v;
    __syncthreads();
    for (int off = 1; off < 1024; off <<= 1) {
        int t = (threadIdx.x >= off) ? sh[threadIdx.x - off] : 0;
        __syncthreads();
        sh[threadIdx.x] += t;
        __syncthreads();
    }
    if (threadIdx.x < nblk) g_bsum[threadIdx.x] = sh[threadIdx.x] - v;
}

__global__ void k_scan3(int n, int E) {
    int i = blockIdx.x * blockDim.x + threadIdx.x;
    if (i < n) {
        int rp = g_rowptr[i] + g_bsum[i / SCAN_BLK];
        g_rowptr[i] = rp;
        g_cursor[i] = rp;
        g_dinv[i]   = rsqrtf((float)g_cnt[i] + 1.0f);
        if (i == n - 1) g_rowptr[n] = E;
    }
}

// ---- tensor-core GEMM body -----------------------------------------------------
__device__ __forceinline__ void mma16816(float c[4], const uint32_t a[4], const uint32_t b[2]) {
    asm volatile(
        "mma.sync.aligned.m16n8k16.row.col.f32.bf16.bf16.f32 "
        "{%0,%1,%2,%3}, {%4,%5,%6,%7}, {%8,%9}, {%0,%1,%2,%3};\n"
        : "+f"(c[0]), "+f"(c[1]), "+f"(c[2]), "+f"(c[3])
        : "r"(a[0]), "r"(a[1]), "r"(a[2]), "r"(a[3]), "r"(b[0]), "r"(b[1]));
}

__device__ __forceinline__ uint32_t pack_bf2(__nv_bfloat16 a, __nv_bfloat16 b) {
    return (uint32_t)__bfloat16_as_ushort(a) | ((uint32_t)__bfloat16_as_ushort(b) << 16);
}

// Block = 128 rows x NOUT cols, 256 threads. K in two 64-chunks.
// LAYER==1: A = x (fp32), epilogue writes RAW acc (dinv deferred to gather1).
// LAYER==2: A = g_agg1h (fp16), dinv*v+b1 fused on load; epilogue scales by dinv.
template <int NOUT, int LAYER>
__device__ void gemm_body(int bid, const float* __restrict__ A_in,
                          const float* __restrict__ bias, int n, __nv_bfloat16* sm)
{
    constexpr int NT = NOUT / 8;
    __nv_bfloat16* Ahi = sm;                    // [128][KP]
    __nv_bfloat16* Alo = Ahi + 128 * KP;
    __nv_bfloat16* Bhi = Alo + 128 * KP;        // [NOUT][KP]
    __nv_bfloat16* Blo = Bhi + NOUT * KP;

    __half* s_out = (LAYER == 1) ? g_s1 : g_s2;
    const __nv_bfloat16* Wh = (LAYER == 1) ? g_w1t_hi : g_w2t_hi;
    const __nv_bfloat16* Wl = (LAYER == 1) ? g_w1t_lo : g_w2t_lo;

    const int tid  = threadIdx.x;
    const int row0 = bid * 128;
    const int w = tid >> 5, lane = tid & 31;
    const int g = lane >> 2, tq = lane & 3;
    const int mrow = w * 16;

    float acc[NT][4];
#pragma unroll
    for (int nt = 0; nt < NT; nt++)
#pragma unroll
        for (int j = 0; j < 4; j++) acc[nt][j] = 0.0f;

#pragma unroll
    for (int kk = 0; kk < 128; kk += 64) {
        if (kk) __syncthreads();

        for (int base = tid * 4; base < 128 * 64; base += 256 * 4) {
            int r = base >> 6, k = base & 63;
            int row = row0 + r;
            float4 v = make_float4(0.f, 0.f, 0.f, 0.f);
            if (row < n) {
                if (LAYER == 1) {
                    v = *reinterpret_cast<const float4*>(&A_in[(size_t)row * 128 + kk + k]);
                } else {
                    uint2 hv = *reinterpret_cast<const uint2*>(&g_agg1h[(size_t)row * 128 + kk + k]);
                    float2 p0 = __half22float2(*reinterpret_cast<__half2*>(&hv.x));
                    float2 p1 = __half22float2(*reinterpret_cast<__half2*>(&hv.y));
                    float d = g_dinv[row];
                    float4 bb = *reinterpret_cast<const float4*>(&bias[kk + k]);
                    v.x = fmaf(d, p0.x, bb.x); v.y = fmaf(d, p0.y, bb.y);
                    v.z = fmaf(d, p1.x, bb.z); v.w = fmaf(d, p1.y, bb.w);
                }
            }
            __nv_bfloat16 h0 = __float2bfloat16(v.x), h1 = __float2bfloat16(v.y);
            __nv_bfloat16 h2 = __float2bfloat16(v.z), h3 = __float2bfloat16(v.w);
            __nv_bfloat16 l0 = __float2bfloat16(v.x - __bfloat162float(h0));
            __nv_bfloat16 l1 = __float2bfloat16(v.y - __bfloat162float(h1));
            __nv_bfloat16 l2 = __float2bfloat16(v.z - __bfloat162float(h2));
            __nv_bfloat16 l3 = __float2bfloat16(v.w - __bfloat162float(h3));
            *reinterpret_cast<uint2*>(&Ahi[r * KP + k]) = make_uint2(pack_bf2(h0, h1), pack_bf2(h2, h3));
            *reinterpret_cast<uint2*>(&Alo[r * KP + k]) = make_uint2(pack_bf2(l0, l1), pack_bf2(l2, l3));
        }
        for (int base = tid * 8; base < NOUT * 64; base += 256 * 8) {
            int nn = base >> 6, k = base & 63;
            *reinterpret_cast<uint4*>(&Bhi[nn * KP + k]) =
                *reinterpret_cast<const uint4*>(&Wh[nn * 128 + kk + k]);
            *reinterpret_cast<uint4*>(&Blo[nn * KP + k]) =
                *reinterpret_cast<const uint4*>(&Wl[nn * 128 + kk + k]);
        }
        __syncthreads();

#pragma unroll
        for (int kt = 0; kt < 4; kt++) {
            const int k0 = kt * 16;
            uint32_t ah[4], al[4];
            const int ra = (mrow + g) * KP + k0 + tq * 2;
            const int rb = (mrow + g + 8) * KP + k0 + tq * 2;
            ah[0] = *reinterpret_cast<const uint32_t*>(&Ahi[ra]);
            ah[1] = *reinterpret_cast<const uint32_t*>(&Ahi[rb]);
            ah[2] = *reinterpret_cast<const uint32_t*>(&Ahi[ra + 8]);
            ah[3] = *reinterpret_cast<const uint32_t*>(&Ahi[rb + 8]);
            al[0] = *reinterpret_cast<const uint32_t*>(&Alo[ra]);
            al[1] = *reinterpret_cast<const uint32_t*>(&Alo[rb]);
            al[2] = *reinterpret_cast<const uint32_t*>(&Alo[ra + 8]);
            al[3] = *reinterpret_cast<const uint32_t*>(&Alo[rb + 8]);
#pragma unroll
            for (int nt = 0; nt < NT; nt++) {
                uint32_t bh[2], bl[2];
                const int rn = (nt * 8 + g) * KP + k0 + tq * 2;
                bh[0] = *reinterpret_cast<const uint32_t*>(&Bhi[rn]);
                bh[1] = *reinterpret_cast<const uint32_t*>(&Bhi[rn + 8]);
                bl[0] = *reinterpret_cast<const uint32_t*>(&Blo[rn]);
                bl[1] = *reinterpret_cast<const uint32_t*>(&Blo[rn + 8]);
                mma16816(acc[nt], ah, bh);
                mma16816(acc[nt], ah, bl);
                mma16816(acc[nt], al, bh);
            }
        }
    }

    const int r0g = row0 + mrow + g;
    const int r1g = r0g + 8;
    float d0 = 1.0f, d1 = 1.0f;
    if (LAYER == 2) {
        d0 = (r0g < n) ? g_dinv[r0g] : 0.f;
        d1 = (r1g < n) ? g_dinv[r1g] : 0.f;
    }
#pragma unroll
    for (int nt = 0; nt < NT; nt++) {
        if (r0g < n) {
            __half2 o = __floats2half2_rn(d0 * acc[nt][0], d0 * acc[nt][1]);
            *reinterpret_cast<__half2*>(&s_out[(size_t)r0g * NOUT + nt * 8 + tq * 2]) = o;
        }
        if (r1g < n) {
            __half2 o = __floats2half2_rn(d1 * acc[nt][2], d1 * acc[nt][3]);
            *reinterpret_cast<__half2*>(&s_out[(size_t)r1g * NOUT + nt * 8 + tq * 2]) = o;
        }
    }
}

// ---- FAT1: degree count (blocks [0,AUX1)) + GEMM1 part A ----------------------
__global__ void __launch_bounds__(256) k_fat1(const int* __restrict__ ew,
                                              const float* __restrict__ x, int n, int E)
{
    extern __shared__ __nv_bfloat16 sm[];
    if (blockIdx.x < AUX1) {
        int is64 = g_is64;
        const int* dst = ew + (size_t)E * (1 + is64);
        for (int i = blockIdx.x * 256 + threadIdx.x; i < E; i += AUX1 * 256)
            atomicAdd(&g_cnt[edge_at(dst, i, is64)], 1);
    } else {
        gemm_body<HID, 1>(blockIdx.x - AUX1, x, nullptr, n, sm);
    }
}

// ---- FAT2: CSR fill (blocks [0,AUX2)) + GEMM1 part B ---------------------------
__global__ void __launch_bounds__(256) k_fat2(const int* __restrict__ ew,
                                              const float* __restrict__ x, int n, int E)
{
    extern __shared__ __nv_bfloat16 sm[];
    if (blockIdx.x < AUX2) {
        int is64 = g_is64;
        const int* src = ew;
        const int* dst = ew + (size_t)E * (1 + is64);
        for (int i = blockIdx.x * 256 + threadIdx.x; i < E; i += AUX2 * 256) {
            int u = edge_at(src, i, is64);
            int v = edge_at(dst, i, is64);
            int pos = atomicAdd(&g_cursor[v], 1);
            g_csr[pos] = u;
        }
    } else {
        gemm_body<HID, 1>(blockIdx.x - AUX2 + GSPLIT, x, nullptr, n, sm);
    }
}

// ---- GEMM2 (plain) -------------------------------------------------------------
__global__ void __launch_bounds__(256) k_tgemm2(const float* __restrict__ bias, int n)
{
    extern __shared__ __nv_bfloat16 sm[];
    gemm_body<ODIM, 2>(blockIdx.x, nullptr, bias, n, sm);
}

// ---- CSR gather ------------------------------------------------------------------
// LAYER==1: agg1h[d] = dinv[d]*s1[d] + sum dinv[u]*s1[u]   (dinv applied here)
// LAYER==2: out[d]   = dinv[d]*(s2[d] + sum s2[u]) + b2
template <int LAYER>
__global__ void k_gather(const float* __restrict__ b2, float* __restrict__ out, int n)
{
    const int lane = threadIdx.x & 31;
    const int wid  = (blockIdx.x * blockDim.x + threadIdx.x) >> 5;
    if (wid >= n) return;

    const int beg = g_rowptr[wid];
    const int end = g_rowptr[wid + 1];

    if (LAYER == 1) {
        const uint2* sp = reinterpret_cast<const uint2*>(g_s1);  // 4 halfs per elem
        const float ds = g_dinv[wid];
        uint2 sv = sp[(size_t)wid * 32 + lane];                  // self loop
        float2 p0 = __half22float2(*reinterpret_cast<__half2*>(&sv.x));
        float2 p1 = __half22float2(*reinterpret_cast<__half2*>(&sv.y));
        float4 a0 = make_float4(ds * p0.x, ds * p0.y, ds * p1.x, ds * p1.y);
        float4 a1 = make_float4(0.f, 0.f, 0.f, 0.f);
        float4 a2 = make_float4(0.f, 0.f, 0.f, 0.f);
        float4 a3 = make_float4(0.f, 0.f, 0.f, 0.f);
        int j = beg;
        for (; j + 4 <= end; j += 4) {
            int u0 = g_csr[j], u1 = g_csr[j + 1], u2 = g_csr[j + 2], u3 = g_csr[j + 3];
            float d0 = g_dinv[u0], d1 = g_dinv[u1], d2 = g_dinv[u2], d3 = g_dinv[u3];
            uint2 v0 = sp[(size_t)u0 * 32 + lane];
            uint2 v1 = sp[(size_t)u1 * 32 + lane];
            uint2 v2 = sp[(size_t)u2 * 32 + lane];
            uint2 v3 = sp[(size_t)u3 * 32 + lane];
            float2 q0, q1;
            q0 = __half22float2(*reinterpret_cast<__half2*>(&v0.x));
            q1 = __half22float2(*reinterpret_cast<__half2*>(&v0.y));
            a0.x = fmaf(d0, q0.x, a0.x); a0.y = fmaf(d0, q0.y, a0.y);
            a0.z = fmaf(d0, q1.x, a0.z); a0.w = fmaf(d0, q1.y, a0.w);
            q0 = __half22float2(*reinterpret_cast<__half2*>(&v1.x));
            q1 = __half22float2(*reinterpret_cast<__half2*>(&v1.y));
            a1.x = fmaf(d1, q0.x, a1.x); a1.y = fmaf(d1, q0.y, a1.y);
            a1.z = fmaf(d1, q1.x, a1.z); a1.w = fmaf(d1, q1.y, a1.w);
            q0 = __half22float2(*reinterpret_cast<__half2*>(&v2.x));
            q1 = __half22float2(*reinterpret_cast<__half2*>(&v2.y));
            a2.x = fmaf(d2, q0.x, a2.x); a2.y = fmaf(d2, q0.y, a2.y);
            a2.z = fmaf(d2, q1.x, a2.z); a2.w = fmaf(d2, q1.y, a2.w);
            q0 = __half22float2(*reinterpret_cast<__half2*>(&v3.x));
            q1 = __half22float2(*reinterpret_cast<__half2*>(&v3.y));
            a3.x = fmaf(d3, q0.x, a3.x); a3.y = fmaf(d3, q0.y, a3.y);
            a3.z = fmaf(d3, q1.x, a3.z); a3.w = fmaf(d3, q1.y, a3.w);
        }
        for (; j < end; j++) {
            int u = g_csr[j];
            float d = g_dinv[u];
            uint2 v = sp[(size_t)u * 32 + lane];
            float2 q0 = __half22float2(*reinterpret_cast<__half2*>(&v.x));
            float2 q1 = __half22float2(*reinterpret_cast<__half2*>(&v.y));
            a0.x = fmaf(d, q0.x, a0.x); a0.y = fmaf(d, q0.y, a0.y);
            a0.z = fmaf(d, q1.x, a0.z); a0.w = fmaf(d, q1.y, a0.w);
        }
        a0.x += a1.x + a2.x + a3.x;
        a0.y += a1.y + a2.y + a3.y;
        a0.z += a1.z + a2.z + a3.z;
        a0.w += a1.w + a2.w + a3.w;
        __half2 o0 = __floats2half2_rn(a0.x, a0.y);
        __half2 o1 = __floats2half2_rn(a0.z, a0.w);
        uint2 ov = make_uint2(*reinterpret_cast<uint32_t*>(&o0), *reinterpret_cast<uint32_t*>(&o1));
        reinterpret_cast<uint2*>(g_agg1h)[(size_t)wid * 32 + lane] = ov;
    } else {
        const uint32_t* sp = reinterpret_cast<const uint32_t*>(g_s2);  // half2 per elem
        uint32_t sv = sp[(size_t)wid * 32 + lane];
        float2 a0 = __half22float2(*reinterpret_cast<__half2*>(&sv));  // self loop
        float2 a1 = make_float2(0.f, 0.f);
        float2 a2 = make_float2(0.f, 0.f);
        float2 a3 = make_float2(0.f, 0.f);
        int j = beg;
        for (; j + 4 <= end; j += 4) {
            int u0 = g_csr[j], u1 = g_csr[j + 1], u2 = g_csr[j + 2], u3 = g_csr[j + 3];
            uint32_t v0 = sp[(size_t)u0 * 32 + lane];
            uint32_t v1 = sp[(size_t)u1 * 32 + lane];
            uint32_t v2 = sp[(size_t)u2 * 32 + lane];
            uint32_t v3 = sp[(size_t)u3 * 32 + lane];
            float2 q;
            q = __half22float2(*reinterpret_cast<__half2*>(&v0)); a0.x += q.x; a0.y += q.y;
            q = __half22float2(*reinterpret_cast<__half2*>(&v1)); a1.x += q.x; a1.y += q.y;
            q = __half22float2(*reinterpret_cast<__half2*>(&v2)); a2.x += q.x; a2.y += q.y;
            q = __half22float2(*reinterpret_cast<__half2*>(&v3)); a3.x += q.x; a3.y += q.y;
        }
        for (; j < end; j++) {
            uint32_t v = sp[(size_t)g_csr[j] * 32 + lane];
            float2 q = __half22float2(*reinterpret_cast<__half2*>(&v));
            a0.x += q.x; a0.y += q.y;
        }
        a0.x += a1.x + a2.x + a3.x;
        a0.y += a1.y + a2.y + a3.y;
        float di = g_dinv[wid];
        float2 r;
        r.x = di * a0.x + b2[lane * 2 + 0];
        r.y = di * a0.y + b2[lane * 2 + 1];
        reinterpret_cast<float2*>(out)[(size_t)wid * 32 + lane] = r;
    }
}

// -----------------------------------------------------------------------------
extern "C" void kernel_launch(void* const* d_in, const int* in_sizes, int n_in,
                              void* d_out, int out_size)
{
    const float* x  = (const float*)d_in[0];
    const int*   ew = (const int*)d_in[1];
    const float* W1 = (const float*)d_in[2];
    const float* b1 = (const float*)d_in[3];
    const float* W2 = (const float*)d_in[4];
    const float* b2 = (const float*)d_in[5];

    const int n = in_sizes[0] / HID;   // 100000
    const int E = in_sizes[1] / 2;     // 1600000
    const int nblk_scan = (n + SCAN_BLK - 1) / SCAN_BLK;

    const int smem1 = (2 * 128 * KP + 2 * HID * KP) * 2;   // 73728 B
    const int smem2 = (2 * 128 * KP + 2 * ODIM * KP) * 2;  // 55296 B
    cudaFuncSetAttribute(k_fat1,  cudaFuncAttributeMaxDynamicSharedMemorySize, smem1);
    cudaFuncSetAttribute(k_fat2,  cudaFuncAttributeMaxDynamicSharedMemorySize, smem1);
    cudaFuncSetAttribute(k_tgemm2, cudaFuncAttributeMaxDynamicSharedMemorySize, smem2);

    const int gblk = (n + 127) / 128;              // 782 gemm1 blocks

    // pre: detect + zero + W conv
    k_pre<<<(n + 255) / 256, 256>>>(ew, W1, W2, n);

    // FAT1: count + gemm1 blocks [0, GSPLIT)
    k_fat1<<<AUX1 + GSPLIT, 256, smem1>>>(ew, x, n, E);

    // scan -> rowptr, cursor, dinv
    k_scan1<<<nblk_scan, SCAN_BLK>>>(n);
    k_scan2<<<1, 1024>>>(nblk_scan);
    k_scan3<<<(n + 255) / 256, 256>>>(n, E);

    // FAT2: fill + gemm1 blocks [GSPLIT, gblk)
    k_fat2<<<AUX2 + (gblk - GSPLIT), 256, smem1>>>(ew, x, n, E);

    // layer-1 gather (applies dinv on both ends)
    k_gather<1><<<(n + 7) / 8, 256>>>(nullptr, nullptr, n);

    // layer 2
    k_tgemm2<<<gblk, 256, smem2>>>(b1, n);
    k_gather<2><<<(n + 7) / 8, 256>>>(b2, (float*)d_out, n);
}